// round 3
// baseline (speedup 1.0000x reference)
#include <cuda_runtime.h>

#define N_NODES 100000
#define CIN 128
#define CHID 128
#define COUT 64

// ---------------- scratch (alloc-free: __device__ globals, 16B-aligned) ----------------
__device__ __align__(16) float g_sum1[(size_t)N_NODES * CIN];    // segment-sum of x
__device__ __align__(16) float g_deg [N_NODES];                  // in-degree
__device__ __align__(16) float g_h   [(size_t)N_NODES * CHID];   // relu(layer1)
__device__ __align__(16) float g_t   [(size_t)N_NODES * COUT];   // h @ W2l
__device__ __align__(16) float g_r   [(size_t)N_NODES * COUT];   // h @ W2r + b2
__device__ __align__(16) float g_sum2[(size_t)N_NODES * COUT];   // segment-sum of t
__device__ int g_is64;                                           // edge_index dtype flag

// ---------------- zero scratch + init flag ----------------
__global__ void zero_kernel() {
    long long i = (long long)blockIdx.x * blockDim.x + threadIdx.x;
    const long long s1 = (long long)N_NODES * CIN;
    const long long s2 = (long long)N_NODES * COUT;
    if (i < s1) g_sum1[i] = 0.f;
    if (i < s2) g_sum2[i] = 0.f;
    if (i < N_NODES) g_deg[i] = 0.f;
    if (i == 0) g_is64 = 1;
}

// ---------------- detect edge_index dtype ----------------
// Interpret buffer as int64. True int64 data (values in [0,N)) stays in range;
// int32 data read as int64 produces values >= 2^32 somewhere -> flag int32.
__global__ void detect_kernel(const long long* __restrict__ ei, long long n) {
    long long i = (long long)blockIdx.x * blockDim.x + threadIdx.x;
    long long stride = (long long)gridDim.x * blockDim.x;
    for (; i < n; i += stride) {
        unsigned long long v = (unsigned long long)ei[i];
        if (v >= (unsigned long long)N_NODES) {
            g_is64 = 0;   // racy but monotone: only ever writes 0
            return;
        }
    }
}

// ---------------- edge aggregation, layer 1: x[src] -> sum1[dst], deg ----------------
__global__ void edge_agg1(const float* __restrict__ x,
                          const void* __restrict__ ei_raw, int E) {
    int e    = (blockIdx.x * blockDim.x + threadIdx.x) >> 5;
    int lane = threadIdx.x & 31;
    if (e >= E) return;
    int src, dst;
    if (g_is64) {
        const long long* ei = (const long long*)ei_raw;
        src = (int)ei[e];
        dst = (int)ei[(size_t)E + e];
    } else {
        const int* ei = (const int*)ei_raw;
        src = ei[e];
        dst = ei[(size_t)E + e];
    }
    if ((unsigned)src >= N_NODES || (unsigned)dst >= N_NODES) return;
    const float* s = x + (size_t)src * CIN + lane * 4;
    float v0 = s[0], v1 = s[1], v2 = s[2], v3 = s[3];
    float* d = g_sum1 + (size_t)dst * CIN + lane * 4;
    atomicAdd(d + 0, v0);
    atomicAdd(d + 1, v1);
    atomicAdd(d + 2, v2);
    atomicAdd(d + 3, v3);
    if (lane == 0) atomicAdd(g_deg + dst, 1.0f);
}

// ---------------- edge aggregation, layer 2: t[src] -> sum2[dst] ----------------
__global__ void edge_agg2(const void* __restrict__ ei_raw, int E) {
    int e    = (blockIdx.x * blockDim.x + threadIdx.x) >> 5;
    int lane = threadIdx.x & 31;
    if (e >= E) return;
    int src, dst;
    if (g_is64) {
        const long long* ei = (const long long*)ei_raw;
        src = (int)ei[e];
        dst = (int)ei[(size_t)E + e];
    } else {
        const int* ei = (const int*)ei_raw;
        src = ei[e];
        dst = ei[(size_t)E + e];
    }
    if ((unsigned)src >= N_NODES || (unsigned)dst >= N_NODES) return;
    const float* s = g_t + (size_t)src * COUT + lane * 2;
    float v0 = s[0], v1 = s[1];
    float* d = g_sum2 + (size_t)dst * COUT + lane * 2;
    atomicAdd(d + 0, v0);
    atomicAdd(d + 1, v1);
}

// ---------------- GEMM layer 1 ----------------
// h = relu([mean | x] @ [W1l ; W1r] + b1)   A:[N,256]  W:[256,128]
// BM=64, BN=128, BK=32 (8 chunks). 256 threads; 8 rows x 4 cols per thread.
#define APITCH 65

__global__ void __launch_bounds__(256) gemm1(const float* __restrict__ x,
                                             const float* __restrict__ W1l,
                                             const float* __restrict__ W1r,
                                             const float* __restrict__ b1) {
    __shared__ float Ws[32 * 128];
    __shared__ float As[32 * APITCH];

    const int tid = threadIdx.x;
    const int block_m = blockIdx.x * 64;

    const int lm   = tid >> 2;
    const int lk0  = (tid & 3) * 8;
    const int node = block_m + lm;
    const bool valid = (node < N_NODES);
    float rdeg = 1.0f;
    if (valid) rdeg = 1.0f / fmaxf(g_deg[node], 1.0f);

    const int c0 = (tid & 31) * 4;
    const int r0 = (tid >> 5) * 8;

    float acc[8][4];
#pragma unroll
    for (int r = 0; r < 8; r++)
#pragma unroll
        for (int c = 0; c < 4; c++) acc[r][c] = 0.f;

    for (int ch = 0; ch < 8; ch++) {
        const int kbase = ch * 32;

#pragma unroll
        for (int i = 0; i < 16; i++) {
            int idx = tid + i * 256;
            int kk = idx >> 7, j = idx & 127;
            int k = kbase + kk;
            Ws[idx] = (k < 128) ? W1l[k * 128 + j] : W1r[(k - 128) * 128 + j];
        }

        float av[8];
        if (valid) {
            if (kbase < 128) {
                const float* p = g_sum1 + (size_t)node * CIN + kbase + lk0;
#pragma unroll
                for (int j = 0; j < 8; j++) av[j] = p[j] * rdeg;
            } else {
                const float* p = x + (size_t)node * CIN + (kbase - 128) + lk0;
#pragma unroll
                for (int j = 0; j < 8; j++) av[j] = p[j];
            }
        } else {
#pragma unroll
            for (int j = 0; j < 8; j++) av[j] = 0.f;
        }
        __syncthreads();
#pragma unroll
        for (int j = 0; j < 8; j++) As[(lk0 + j) * APITCH + lm] = av[j];
        __syncthreads();

#pragma unroll
        for (int kk = 0; kk < 32; kk++) {
            float w0 = Ws[kk * 128 + c0 + 0];
            float w1 = Ws[kk * 128 + c0 + 1];
            float w2 = Ws[kk * 128 + c0 + 2];
            float w3 = Ws[kk * 128 + c0 + 3];
            const float* ar = &As[kk * APITCH + r0];
#pragma unroll
            for (int r = 0; r < 8; r++) {
                float a = ar[r];
                acc[r][0] += a * w0;
                acc[r][1] += a * w1;
                acc[r][2] += a * w2;
                acc[r][3] += a * w3;
            }
        }
        __syncthreads();
    }

    float b0 = b1[c0], bb1 = b1[c0 + 1], b2v = b1[c0 + 2], b3 = b1[c0 + 3];
#pragma unroll
    for (int r = 0; r < 8; r++) {
        int n = block_m + r0 + r;
        if (n < N_NODES) {
            float* o = g_h + (size_t)n * CHID + c0;
            o[0] = fmaxf(acc[r][0] + b0, 0.f);
            o[1] = fmaxf(acc[r][1] + bb1, 0.f);
            o[2] = fmaxf(acc[r][2] + b2v, 0.f);
            o[3] = fmaxf(acc[r][3] + b3, 0.f);
        }
    }
}

// ---------------- GEMM layer 2 ----------------
// [t | r] = h @ [W2l | W2r] (+ [0 | b2])   A:[N,128]  W:[128,128]
__global__ void __launch_bounds__(256) gemm2(const float* __restrict__ W2l,
                                             const float* __restrict__ W2r,
                                             const float* __restrict__ b2) {
    __shared__ float Ws[32 * 128];
    __shared__ float As[32 * APITCH];

    const int tid = threadIdx.x;
    const int block_m = blockIdx.x * 64;

    const int lm   = tid >> 2;
    const int lk0  = (tid & 3) * 8;
    const int node = block_m + lm;
    const bool valid = (node < N_NODES);

    const int c0 = (tid & 31) * 4;
    const int r0 = (tid >> 5) * 8;

    float acc[8][4];
#pragma unroll
    for (int r = 0; r < 8; r++)
#pragma unroll
        for (int c = 0; c < 4; c++) acc[r][c] = 0.f;

    for (int ch = 0; ch < 4; ch++) {
        const int kbase = ch * 32;

#pragma unroll
        for (int i = 0; i < 16; i++) {
            int idx = tid + i * 256;
            int kk = idx >> 7, j = idx & 127;
            int k = kbase + kk;
            Ws[idx] = (j < 64) ? W2l[k * 64 + j] : W2r[k * 64 + (j - 64)];
        }

        float av[8];
        if (valid) {
            const float* p = g_h + (size_t)node * CHID + kbase + lk0;
#pragma unroll
            for (int j = 0; j < 8; j++) av[j] = p[j];
        } else {
#pragma unroll
            for (int j = 0; j < 8; j++) av[j] = 0.f;
        }
        __syncthreads();
#pragma unroll
        for (int j = 0; j < 8; j++) As[(lk0 + j) * APITCH + lm] = av[j];
        __syncthreads();

#pragma unroll
        for (int kk = 0; kk < 32; kk++) {
            float w0 = Ws[kk * 128 + c0 + 0];
            float w1 = Ws[kk * 128 + c0 + 1];
            float w2 = Ws[kk * 128 + c0 + 2];
            float w3 = Ws[kk * 128 + c0 + 3];
            const float* ar = &As[kk * APITCH + r0];
#pragma unroll
            for (int r = 0; r < 8; r++) {
                float a = ar[r];
                acc[r][0] += a * w0;
                acc[r][1] += a * w1;
                acc[r][2] += a * w2;
                acc[r][3] += a * w3;
            }
        }
        __syncthreads();
    }

    if (c0 < 64) {
#pragma unroll
        for (int r = 0; r < 8; r++) {
            int n = block_m + r0 + r;
            if (n < N_NODES) {
                float* o = g_t + (size_t)n * COUT + c0;
                o[0] = acc[r][0]; o[1] = acc[r][1];
                o[2] = acc[r][2]; o[3] = acc[r][3];
            }
        }
    } else {
        int cc = c0 - 64;
        float b0 = b2[cc], bb1 = b2[cc + 1], b2v = b2[cc + 2], b3 = b2[cc + 3];
#pragma unroll
        for (int r = 0; r < 8; r++) {
            int n = block_m + r0 + r;
            if (n < N_NODES) {
                float* o = g_r + (size_t)n * COUT + cc;
                o[0] = acc[r][0] + b0;  o[1] = acc[r][1] + bb1;
                o[2] = acc[r][2] + b2v; o[3] = acc[r][3] + b3;
            }
        }
    }
}

// ---------------- final: out = sum2/clip(deg,1) + r ----------------
__global__ void final_kernel(float* __restrict__ out) {
    int i = blockIdx.x * blockDim.x + threadIdx.x;
    if (i >= N_NODES * COUT) return;
    int n = i >> 6;
    out[i] = g_sum2[i] / fmaxf(g_deg[n], 1.0f) + g_r[i];
}

// ---------------- launch ----------------
extern "C" void kernel_launch(void* const* d_in, const int* in_sizes, int n_in,
                              void* d_out, int out_size) {
    const float* x   = (const float*)d_in[0];
    const void*  ei  = d_in[1];
    const float* W1l = (const float*)d_in[2];
    const float* W1r = (const float*)d_in[3];
    const float* b1  = (const float*)d_in[4];
    const float* W2l = (const float*)d_in[5];
    const float* W2r = (const float*)d_in[6];
    const float* b2  = (const float*)d_in[7];
    float* out = (float*)d_out;

    const int E = in_sizes[1] / 2;

    {
        long long tot = (long long)N_NODES * CIN;
        int blocks = (int)((tot + 255) / 256);
        zero_kernel<<<blocks, 256>>>();
    }
    {
        // NOTE: if buffer is int32, reading the second half as int64 would run
        // past nothing (same byte count read as int64 covers exactly the buffer
        // if it were int64; for int32 the buffer is half that size). So scan
        // only the first quarter of the int64 view — guaranteed in-bounds for
        // both dtypes and still covers 800K values (plenty of evidence).
        long long n64_safe = (long long)E / 2;
        detect_kernel<<<1024, 256>>>((const long long*)ei, n64_safe);
    }
    {
        long long threads = (long long)E * 32;
        int blocks = (int)((threads + 255) / 256);
        edge_agg1<<<blocks, 256>>>(x, ei, E);
    }
    {
        int blocks = (N_NODES + 63) / 64;
        gemm1<<<blocks, 256>>>(x, W1l, W1r, b1);
        gemm2<<<blocks, 256>>>(W2l, W2r, b2);
    }
    {
        long long threads = (long long)E * 32;
        int blocks = (int)((threads + 255) / 256);
        edge_agg2<<<blocks, 256>>>(ei, E);
    }
    {
        int blocks = (N_NODES * COUT + 255) / 256;
        final_kernel<<<blocks, 256>>>(out);
    }
}

// round 4
// speedup vs baseline: 1.6859x; 1.6859x over previous
#include <cuda_runtime.h>

#define N_NODES 100000
#define CIN 128
#define CHID 128
#define COUT 64

// ---------------- scratch (alloc-free: __device__ globals, 16B-aligned) ----------------
__device__ __align__(16) float g_sum1[(size_t)N_NODES * CIN];
__device__ __align__(16) float g_deg [N_NODES];
__device__ __align__(16) float g_h   [(size_t)N_NODES * CHID];
__device__ __align__(16) float g_t   [(size_t)N_NODES * COUT];
__device__ __align__(16) float g_r   [(size_t)N_NODES * COUT];
__device__ __align__(16) float g_sum2[(size_t)N_NODES * COUT];
__device__ int g_is64;

// ---------------- helpers: packed f32x2 ----------------
__device__ __forceinline__ unsigned long long dupf2(float v) {
    unsigned long long r;
    asm("mov.b64 %0, {%1, %1};" : "=l"(r) : "r"(__float_as_uint(v)));
    return r;
}
__device__ __forceinline__ void fma2(unsigned long long& d,
                                     unsigned long long a, unsigned long long b) {
    asm("fma.rn.f32x2 %0, %1, %2, %0;" : "+l"(d) : "l"(a), "l"(b));
}
__device__ __forceinline__ void unpack2(unsigned long long p, float& lo, float& hi) {
    unsigned int l, h;
    asm("mov.b64 {%0, %1}, %2;" : "=r"(l), "=r"(h) : "l"(p));
    lo = __uint_as_float(l); hi = __uint_as_float(h);
}

// ---------------- zero scratch + init flag ----------------
__global__ void zero_kernel() {
    long long i = (long long)blockIdx.x * blockDim.x + threadIdx.x;
    const long long s1 = (long long)(N_NODES * (CIN / 4));   // float4 counts
    const long long s2 = (long long)(N_NODES * (COUT / 4));
    float4 z = {0.f, 0.f, 0.f, 0.f};
    if (i < s1) reinterpret_cast<float4*>(g_sum1)[i] = z;
    if (i < s2) reinterpret_cast<float4*>(g_sum2)[i] = z;
    if (i < N_NODES) g_deg[i] = 0.f;
    if (i == 0) g_is64 = 1;
}

// ---------------- detect edge_index dtype ----------------
__global__ void detect_kernel(const long long* __restrict__ ei, long long n) {
    long long i = (long long)blockIdx.x * blockDim.x + threadIdx.x;
    long long stride = (long long)gridDim.x * blockDim.x;
    for (; i < n; i += stride) {
        unsigned long long v = (unsigned long long)ei[i];
        if (v >= (unsigned long long)N_NODES) { g_is64 = 0; return; }
    }
}

// ---------------- edge aggregation, layer 1 ----------------
// warp per edge: 32 lanes x float4 = 128 ch; red.global.add.v4.f32
__global__ void edge_agg1(const float* __restrict__ x,
                          const void* __restrict__ ei_raw, int E) {
    int e    = (blockIdx.x * blockDim.x + threadIdx.x) >> 5;
    int lane = threadIdx.x & 31;
    if (e >= E) return;
    int src, dst;
    if (g_is64) {
        const long long* ei = (const long long*)ei_raw;
        src = (int)ei[e]; dst = (int)ei[(size_t)E + e];
    } else {
        const int* ei = (const int*)ei_raw;
        src = ei[e]; dst = ei[(size_t)E + e];
    }
    if ((unsigned)src >= N_NODES || (unsigned)dst >= N_NODES) return;
    float4 v = *reinterpret_cast<const float4*>(x + (size_t)src * CIN + lane * 4);
    float* d = g_sum1 + (size_t)dst * CIN + lane * 4;
    asm volatile("red.global.add.v4.f32 [%0], {%1, %2, %3, %4};"
                 :: "l"(d), "f"(v.x), "f"(v.y), "f"(v.z), "f"(v.w) : "memory");
    if (lane == 0) atomicAdd(g_deg + dst, 1.0f);
}

// ---------------- edge aggregation, layer 2 ----------------
// 16 lanes per edge x float4 = 64 ch; two edges per warp
__global__ void edge_agg2(const void* __restrict__ ei_raw, int E) {
    int idx = blockIdx.x * blockDim.x + threadIdx.x;
    int e   = idx >> 4;
    int l   = idx & 15;
    if (e >= E) return;
    int src, dst;
    if (g_is64) {
        const long long* ei = (const long long*)ei_raw;
        src = (int)ei[e]; dst = (int)ei[(size_t)E + e];
    } else {
        const int* ei = (const int*)ei_raw;
        src = ei[e]; dst = ei[(size_t)E + e];
    }
    if ((unsigned)src >= N_NODES || (unsigned)dst >= N_NODES) return;
    float4 v = *reinterpret_cast<const float4*>(g_t + (size_t)src * COUT + l * 4);
    float* d = g_sum2 + (size_t)dst * COUT + l * 4;
    asm volatile("red.global.add.v4.f32 [%0], {%1, %2, %3, %4};"
                 :: "l"(d), "f"(v.x), "f"(v.y), "f"(v.z), "f"(v.w) : "memory");
}

// ---------------- GEMM layer 1 (FFMA2) ----------------
// h = relu([mean | x] @ [W1l ; W1r] + b1)   A:[N,256]  W:[256,128]
// BM=64, BN=128, BK=32. 256 threads; per thread 8 rows x 4 cols as 4x4 f32x2.
#define APITCH 66   // even: enables 8B LDS of row pairs; 16B-aligned base

__global__ void __launch_bounds__(256) gemm1(const float* __restrict__ x,
                                             const float* __restrict__ W1l,
                                             const float* __restrict__ W1r,
                                             const float* __restrict__ b1) {
    __shared__ __align__(16) float Ws[32 * 128];
    __shared__ __align__(16) float As[32 * APITCH];

    const int tid = threadIdx.x;
    const int block_m = blockIdx.x * 64;

    const int lm   = tid >> 2;          // node within tile (0..63)
    const int lk0  = (tid & 3) * 8;     // k-offset (0,8,16,24)
    const int node = block_m + lm;
    const bool valid = (node < N_NODES);
    float rdeg = 1.0f;
    if (valid) rdeg = 1.0f / fmaxf(g_deg[node], 1.0f);

    const int c0 = (tid & 31) * 4;      // output cols
    const int r0 = (tid >> 5) * 8;      // output rows (even, mult of 8)

    unsigned long long acc[4][4];       // [col][row-pair]
#pragma unroll
    for (int c = 0; c < 4; c++)
#pragma unroll
        for (int p = 0; p < 4; p++) acc[c][p] = 0ull;

    for (int ch = 0; ch < 8; ch++) {
        const int kbase = ch * 32;

#pragma unroll
        for (int i = 0; i < 16; i++) {
            int idx = tid + i * 256;
            int kk = idx >> 7, j = idx & 127;
            int k = kbase + kk;
            Ws[idx] = (k < 128) ? W1l[k * 128 + j] : W1r[(k - 128) * 128 + j];
        }

        float av[8];
        if (valid) {
            if (kbase < 128) {
                const float* p = g_sum1 + (size_t)node * CIN + kbase + lk0;
#pragma unroll
                for (int j = 0; j < 8; j++) av[j] = p[j] * rdeg;
            } else {
                const float* p = x + (size_t)node * CIN + (kbase - 128) + lk0;
#pragma unroll
                for (int j = 0; j < 8; j++) av[j] = p[j];
            }
        } else {
#pragma unroll
            for (int j = 0; j < 8; j++) av[j] = 0.f;
        }
        __syncthreads();
#pragma unroll
        for (int j = 0; j < 8; j++) As[(lk0 + j) * APITCH + lm] = av[j];
        __syncthreads();

#pragma unroll
        for (int kk = 0; kk < 32; kk++) {
            float4 w = *reinterpret_cast<const float4*>(&Ws[kk * 128 + c0]);
            unsigned long long wd[4];
            wd[0] = dupf2(w.x); wd[1] = dupf2(w.y);
            wd[2] = dupf2(w.z); wd[3] = dupf2(w.w);
            const unsigned long long* ap =
                reinterpret_cast<const unsigned long long*>(&As[kk * APITCH + r0]);
            unsigned long long a01 = ap[0], a23 = ap[1], a45 = ap[2], a67 = ap[3];
#pragma unroll
            for (int c = 0; c < 4; c++) {
                fma2(acc[c][0], wd[c], a01);
                fma2(acc[c][1], wd[c], a23);
                fma2(acc[c][2], wd[c], a45);
                fma2(acc[c][3], wd[c], a67);
            }
        }
        __syncthreads();
    }

    float bv[4] = {b1[c0], b1[c0 + 1], b1[c0 + 2], b1[c0 + 3]};
    float res[8][4];
#pragma unroll
    for (int c = 0; c < 4; c++)
#pragma unroll
        for (int p = 0; p < 4; p++)
            unpack2(acc[c][p], res[2 * p][c], res[2 * p + 1][c]);
#pragma unroll
    for (int r = 0; r < 8; r++) {
        int n = block_m + r0 + r;
        if (n < N_NODES) {
            float4 o;
            o.x = fmaxf(res[r][0] + bv[0], 0.f);
            o.y = fmaxf(res[r][1] + bv[1], 0.f);
            o.z = fmaxf(res[r][2] + bv[2], 0.f);
            o.w = fmaxf(res[r][3] + bv[3], 0.f);
            *reinterpret_cast<float4*>(g_h + (size_t)n * CHID + c0) = o;
        }
    }
}

// ---------------- GEMM layer 2 (FFMA2) ----------------
// [t | r] = h @ [W2l | W2r] (+ [0 | b2])   A:[N,128]  W:[128,128]
__global__ void __launch_bounds__(256) gemm2(const float* __restrict__ W2l,
                                             const float* __restrict__ W2r,
                                             const float* __restrict__ b2) {
    __shared__ __align__(16) float Ws[32 * 128];
    __shared__ __align__(16) float As[32 * APITCH];

    const int tid = threadIdx.x;
    const int block_m = blockIdx.x * 64;

    const int lm   = tid >> 2;
    const int lk0  = (tid & 3) * 8;
    const int node = block_m + lm;
    const bool valid = (node < N_NODES);

    const int c0 = (tid & 31) * 4;
    const int r0 = (tid >> 5) * 8;

    unsigned long long acc[4][4];
#pragma unroll
    for (int c = 0; c < 4; c++)
#pragma unroll
        for (int p = 0; p < 4; p++) acc[c][p] = 0ull;

    for (int ch = 0; ch < 4; ch++) {
        const int kbase = ch * 32;

#pragma unroll
        for (int i = 0; i < 16; i++) {
            int idx = tid + i * 256;
            int kk = idx >> 7, j = idx & 127;
            int k = kbase + kk;
            Ws[idx] = (j < 64) ? W2l[k * 64 + j] : W2r[k * 64 + (j - 64)];
        }

        float av[8];
        if (valid) {
            const float* p = g_h + (size_t)node * CHID + kbase + lk0;
#pragma unroll
            for (int j = 0; j < 8; j++) av[j] = p[j];
        } else {
#pragma unroll
            for (int j = 0; j < 8; j++) av[j] = 0.f;
        }
        __syncthreads();
#pragma unroll
        for (int j = 0; j < 8; j++) As[(lk0 + j) * APITCH + lm] = av[j];
        __syncthreads();

#pragma unroll
        for (int kk = 0; kk < 32; kk++) {
            float4 w = *reinterpret_cast<const float4*>(&Ws[kk * 128 + c0]);
            unsigned long long wd[4];
            wd[0] = dupf2(w.x); wd[1] = dupf2(w.y);
            wd[2] = dupf2(w.z); wd[3] = dupf2(w.w);
            const unsigned long long* ap =
                reinterpret_cast<const unsigned long long*>(&As[kk * APITCH + r0]);
            unsigned long long a01 = ap[0], a23 = ap[1], a45 = ap[2], a67 = ap[3];
#pragma unroll
            for (int c = 0; c < 4; c++) {
                fma2(acc[c][0], wd[c], a01);
                fma2(acc[c][1], wd[c], a23);
                fma2(acc[c][2], wd[c], a45);
                fma2(acc[c][3], wd[c], a67);
            }
        }
        __syncthreads();
    }

    float res[8][4];
#pragma unroll
    for (int c = 0; c < 4; c++)
#pragma unroll
        for (int p = 0; p < 4; p++)
            unpack2(acc[c][p], res[2 * p][c], res[2 * p + 1][c]);

    if (c0 < 64) {
#pragma unroll
        for (int r = 0; r < 8; r++) {
            int n = block_m + r0 + r;
            if (n < N_NODES) {
                float4 o = {res[r][0], res[r][1], res[r][2], res[r][3]};
                *reinterpret_cast<float4*>(g_t + (size_t)n * COUT + c0) = o;
            }
        }
    } else {
        int cc = c0 - 64;
        float bv[4] = {b2[cc], b2[cc + 1], b2[cc + 2], b2[cc + 3]};
#pragma unroll
        for (int r = 0; r < 8; r++) {
            int n = block_m + r0 + r;
            if (n < N_NODES) {
                float4 o = {res[r][0] + bv[0], res[r][1] + bv[1],
                            res[r][2] + bv[2], res[r][3] + bv[3]};
                *reinterpret_cast<float4*>(g_r + (size_t)n * COUT + cc) = o;
            }
        }
    }
}

// ---------------- final: out = sum2/clip(deg,1) + r ----------------
__global__ void final_kernel(float* __restrict__ out) {
    int i = blockIdx.x * blockDim.x + threadIdx.x;
    if (i >= N_NODES * (COUT / 4)) return;
    int n = i >> 4;   // 16 float4 per node
    float rd = 1.0f / fmaxf(g_deg[n], 1.0f);
    float4 s = reinterpret_cast<const float4*>(g_sum2)[i];
    float4 r = reinterpret_cast<const float4*>(g_r)[i];
    float4 o = {s.x * rd + r.x, s.y * rd + r.y, s.z * rd + r.z, s.w * rd + r.w};
    reinterpret_cast<float4*>(out)[i] = o;
}

// ---------------- launch ----------------
extern "C" void kernel_launch(void* const* d_in, const int* in_sizes, int n_in,
                              void* d_out, int out_size) {
    const float* x   = (const float*)d_in[0];
    const void*  ei  = d_in[1];
    const float* W1l = (const float*)d_in[2];
    const float* W1r = (const float*)d_in[3];
    const float* b1  = (const float*)d_in[4];
    const float* W2l = (const float*)d_in[5];
    const float* W2r = (const float*)d_in[6];
    const float* b2  = (const float*)d_in[7];
    float* out = (float*)d_out;

    const int E = in_sizes[1] / 2;

    {
        long long tot = (long long)N_NODES * (CIN / 4);
        int blocks = (int)((tot + 255) / 256);
        zero_kernel<<<blocks, 256>>>();
    }
    {
        long long n64_safe = (long long)E / 2;   // in-bounds for both dtypes
        detect_kernel<<<1024, 256>>>((const long long*)ei, n64_safe);
    }
    {
        long long threads = (long long)E * 32;
        int blocks = (int)((threads + 255) / 256);
        edge_agg1<<<blocks, 256>>>(x, ei, E);
    }
    {
        int blocks = (N_NODES + 63) / 64;
        gemm1<<<blocks, 256>>>(x, W1l, W1r, b1);
        gemm2<<<blocks, 256>>>(W2l, W2r, b2);
    }
    {
        long long threads = (long long)E * 16;
        int blocks = (int)((threads + 255) / 256);
        edge_agg2<<<blocks, 256>>>(ei, E);
    }
    {
        int blocks = (N_NODES * (COUT / 4) + 255) / 256;
        final_kernel<<<blocks, 256>>>(out);
    }
}